// round 14
// baseline (speedup 1.0000x reference)
#include <cuda_runtime.h>
#include <cuda_bf16.h>
#include <cstdint>

#define B_   32
#define S_   512
#define D_   768
#define EPS_ 1e-8f

#define KC    64
#define NCH   (D_ / KC)          // 12

// ---------------- device scratch ----------------
// compacted, chunk-tiled, pre-swizzled bf16: [b][kc][slot][64], 128B rows
__device__ __align__(16) __nv_bfloat16 g_n1t[B_ * S_ * D_];
__device__ __align__(16) __nv_bfloat16 g_n2t[B_ * S_ * D_];
__device__ int g_idx1[B_ * S_], g_idx2[B_ * S_];    // slot -> original row
__device__ int g_cnt1[B_], g_cnt2[B_];
__device__ unsigned g_rowmax[B_ * S_];   // order-preserving mapped fp32
__device__ unsigned g_colmax[B_ * S_];
__device__ int      g_arrive[B_];

// ---------------- helpers ----------------
__device__ __forceinline__ uint32_t smem_u32(const void* p) {
    uint32_t a;
    asm("{ .reg .u64 t; cvta.to.shared.u64 t, %1; cvt.u32.u64 %0, t; }" : "=r"(a) : "l"(p));
    return a;
}
__device__ __forceinline__ unsigned fmap(float x) {
    int i = __float_as_int(x);
    return (unsigned)(i ^ ((i >> 31) | 0x80000000));
}
__device__ __forceinline__ float fumap(unsigned u) {
    int i = (int)(u ^ ((u & 0x80000000u) ? 0x80000000u : 0xFFFFFFFFu));
    return __int_as_float(i);
}

#define MBARRIER_INIT(addr, cnt) \
    asm volatile("mbarrier.init.shared.b64 [%0], %1;" :: "r"(addr), "r"(cnt) : "memory")
#define MBARRIER_EXPECT_TX(addr, bytes) \
    asm volatile("mbarrier.arrive.expect_tx.shared.b64 _, [%0], %1;" :: "r"(addr), "r"(bytes) : "memory")
#define MBARRIER_ARRIVE(addr) \
    asm volatile("mbarrier.arrive.shared.b64 _, [%0];" :: "r"(addr) : "memory")
#define MBARRIER_WAIT_PARITY(mbar_addr, phase_parity) do {                          \
    uint32_t _mbar = (uint32_t)(mbar_addr);                                         \
    uint32_t _par  = (uint32_t)(phase_parity);                                      \
    asm volatile(                                                                   \
        "{\n\t.reg .pred P1;\n\t"                                                   \
        "WAIT_LOOP_%=:\n\t"                                                         \
        "mbarrier.try_wait.parity.acquire.cta.shared::cta.b64 P1, [%0], %1, 0x989680;\n\t" \
        "@P1 bra.uni WAIT_DONE_%=;\n\t"                                             \
        "bra.uni WAIT_LOOP_%=;\n\t"                                                 \
        "WAIT_DONE_%=:\n\t}"                                                        \
        :: "r"(_mbar), "r"(_par) : "memory");                                       \
} while (0)

#define BULK_LOAD(dst, src, size, mbar) \
    asm volatile("cp.async.bulk.shared::cluster.global.mbarrier::complete_tx::bytes " \
                 "[%0], [%1], %2, [%3];" \
                 :: "r"(dst), "l"(src), "r"(size), "r"(mbar) : "memory")

#define LDMATRIX_X4(r0, r1, r2, r3, addr) \
    asm volatile("ldmatrix.sync.aligned.m8n8.x4.shared.b16 {%0,%1,%2,%3}, [%4];" \
                 : "=r"(r0), "=r"(r1), "=r"(r2), "=r"(r3) : "r"(addr))

// ---------------- kernel 1: normalize valid rows + in-block mask prefix ----------
// block 256 = 8 warps = 8 rows of one batch; each block re-derives its batch's
// 512-entry mask prefix (ballot scan) — no separate prefix kernel.
__global__ __launch_bounds__(256) void normalize_kernel(const float* __restrict__ e1,
                                                        const float* __restrict__ e2,
                                                        const int* __restrict__ mask1,
                                                        const int* __restrict__ mask2) {
    const int lane = threadIdx.x & 31;
    const int wrp  = threadIdx.x >> 5;
    const int grow = blockIdx.x * 8 + wrp;      // 0..16383
    const int b    = grow >> 9;
    const int r    = grow & 511;
    const int side = blockIdx.y;

    if (side == 0 && blockIdx.x < 64) {
        int t = blockIdx.x * 256 + threadIdx.x;   // covers exactly 16384
        g_rowmax[t] = 0u;
        g_colmax[t] = 0u;
        if (t < B_) g_arrive[t] = 0;
    }

    const int* m = side ? mask2 : mask1;

    __shared__ unsigned sball[16];
    __shared__ int segoff[16];

    {   // block-wide ballot scan of this batch's 512 mask entries
        int ra = threadIdx.x;                     // rows 0..255 and 256..511
        int va = (m[b * S_ + ra] != 0);
        int vb = (m[b * S_ + ra + 256] != 0);
        unsigned ba = __ballot_sync(0xffffffffu, va);
        unsigned bb = __ballot_sync(0xffffffffu, vb);
        if (lane == 0) { sball[wrp] = ba; sball[8 + wrp] = bb; }
    }
    __syncthreads();
    if (threadIdx.x == 0) {
        int run = 0;
        #pragma unroll
        for (int i = 0; i < 16; i++) { segoff[i] = run; run += __popc(sball[i]); }
        if (side == 0) g_cnt1[b] = run; else g_cnt2[b] = run;   // redundant same-value writes
    }
    __syncthreads();

    const int seg = r >> 5, bit = r & 31;
    if (!((sball[seg] >> bit) & 1u)) return;
    const int slot = segoff[seg] + __popc(sball[seg] & ((1u << bit) - 1u));
    if (lane == 0) (side ? g_idx2 : g_idx1)[b * S_ + slot] = r;

    const float* src = (side ? e2 : e1) + (size_t)grow * D_;
    __nv_bfloat16* dstBase = side ? g_n2t : g_n1t;

    float4 v[6];
    float ss = 0.0f;
    #pragma unroll
    for (int k = 0; k < 6; k++) {
        v[k] = __ldcs((const float4*)(src + lane * 4 + k * 128));
        ss += v[k].x * v[k].x + v[k].y * v[k].y + v[k].z * v[k].z + v[k].w * v[k].w;
    }
    #pragma unroll
    for (int o = 16; o; o >>= 1) ss += __shfl_xor_sync(0xffffffffu, ss, o);

    const float s = 1.0f / fmaxf(sqrtf(ss), EPS_);
    const int swz = (slot & 7) << 3;              // bf16-unit swizzle within 64-col row

    #pragma unroll
    for (int k = 0; k < 6; k++) {
        int cg = lane * 4 + k * 128;
        int kc = cg >> 6;
        int c  = cg & 63;
        size_t idx = ((size_t)(b * NCH + kc) * S_ + slot) * 64 + (size_t)(c ^ swz);
        *(__nv_bfloat162*)(dstBase + idx)     = __floats2bfloat162_rn(v[k].x * s, v[k].y * s);
        *(__nv_bfloat162*)(dstBase + idx + 2) = __floats2bfloat162_rn(v[k].z * s, v[k].w * s);
    }
}

// ---------------- kernel 2: compacted bulk-copy HMMA GEMM, warp-quadrant skip ----
// CTA tile 128x128, 4 warps 2(m)x2(n), warp tile 64x64, mma m16n8k16 bf16.
// grid (4,4,32); CTAs beyond counts exit to finalize; warps whose 64x64
// quadrant is beyond counts skip compute but keep pipeline pacing.
#define TILE_BYTES  16384                 // 128 rows x 128B (A and B)
#define STAGE_BYTES (2 * TILE_BYTES)
#define SM_BUF      1024
#define SMEM_TOTAL  (SM_BUF + 3 * STAGE_BYTES)   // 99328

__global__ __launch_bounds__(128, 2) void gemm_max_kernel(const int* __restrict__ mask1,
                                                          const int* __restrict__ mask2,
                                                          float* __restrict__ out) {
    extern __shared__ char smem[];
    const uint32_t sbase = smem_u32(smem);

    const int tid  = threadIdx.x;
    const int lane = tid & 31;
    const int g    = lane >> 2;
    const int tg   = lane & 3;
    const int warp = tid >> 5;        // 0..3
    const int wm   = warp >> 1;       // 0..1
    const int wn   = warp & 1;        // 0..1

    const int b  = blockIdx.z;
    const int i0 = blockIdx.y * 128;
    const int j0 = blockIdx.x * 128;
    const int bid = blockIdx.x + 4 * blockIdx.y + 16 * b;
    const int off = bid % NCH;

    const int c1 = g_cnt1[b];
    const int c2 = g_cnt2[b];
    const bool active = (i0 < c1) && (j0 < c2);
    const bool wAct = active && (i0 + wm * 64 < c1) && (j0 + wn * 64 < c2);

    if (active) {
        float c[4][8][4];
        #pragma unroll
        for (int mf = 0; mf < 4; mf++)
            #pragma unroll
            for (int nf = 0; nf < 8; nf++)
                #pragma unroll
                for (int e = 0; e < 4; e++) c[mf][nf][e] = 0.0f;

        uint32_t mbF[3], mbE[3], sA[3], sB[3];
        #pragma unroll
        for (int s = 0; s < 3; s++) {
            mbF[s] = sbase + s * 8;
            mbE[s] = sbase + 24 + s * 8;
            sA[s] = sbase + SM_BUF + s * STAGE_BYTES;
            sB[s] = sA[s] + TILE_BYTES;
        }

        if (tid == 0) {
            #pragma unroll
            for (int s = 0; s < 3; s++) {
                MBARRIER_INIT(mbF[s], 1);
                MBARRIER_INIT(mbE[s], 4);         // one arrive per warp
            }
        }
        __syncthreads();

        const __nv_bfloat16* gA0 = g_n1t + ((size_t)(b * NCH) * S_ + i0) * 64;
        const __nv_bfloat16* gB0 = g_n2t + ((size_t)(b * NCH) * S_ + j0) * 64;
        const size_t CH_STRIDE = (size_t)S_ * 64;

        if (tid == 0) {
            #pragma unroll
            for (int p = 0; p < 2; p++) {
                const int cc = (p + off) % NCH;
                MBARRIER_EXPECT_TX(mbF[p], STAGE_BYTES);
                BULK_LOAD(sA[p], gA0 + (size_t)cc * CH_STRIDE, TILE_BYTES, mbF[p]);
                BULK_LOAD(sB[p], gB0 + (size_t)cc * CH_STRIDE, TILE_BYTES, mbF[p]);
            }
        }

        const int ar = wm * 64 + (lane & 15);
        const uint32_t arow = (uint32_t)ar * 128;
        const uint32_t aswz = (uint32_t)(ar & 7) << 4;
        const uint32_t ac0  = (uint32_t)(lane >> 4) * 16;

        const int br = wn * 64 + (lane & 7) + ((lane >> 4) << 3);
        const uint32_t brow = (uint32_t)br * 128;
        const uint32_t bswz = (uint32_t)(br & 7) << 4;
        const uint32_t bc0  = (uint32_t)((lane >> 3) & 1) * 16;

        unsigned af[2][4][4], bfr[2][8][2];

        #pragma unroll 1
        for (int ch = 0; ch < NCH; ch++) {
            const int stage = ch % 3;

            if (tid == 0 && ch + 2 < NCH) {
                const int cn = ch + 2;
                const int s2 = cn % 3;
                MBARRIER_WAIT_PARITY(mbE[s2], ((cn / 3) & 1) ^ 1);
                const int cc2 = (cn + off) % NCH;
                MBARRIER_EXPECT_TX(mbF[s2], STAGE_BYTES);
                BULK_LOAD(sA[s2], gA0 + (size_t)cc2 * CH_STRIDE, TILE_BYTES, mbF[s2]);
                BULK_LOAD(sB[s2], gB0 + (size_t)cc2 * CH_STRIDE, TILE_BYTES, mbF[s2]);
            }

            MBARRIER_WAIT_PARITY(mbF[stage], (ch / 3) & 1);

            if (wAct) {
                const uint32_t abase = sA[stage] + arow;
                const uint32_t bbase = sB[stage] + brow;

                #pragma unroll
                for (int mf = 0; mf < 4; mf++)
                    LDMATRIX_X4(af[0][mf][0], af[0][mf][1], af[0][mf][2], af[0][mf][3],
                                abase + mf * 2048 + (ac0 ^ aswz));
                #pragma unroll
                for (int p = 0; p < 4; p++) {
                    unsigned r0, r1, r2, r3;
                    LDMATRIX_X4(r0, r1, r2, r3, bbase + p * 2048 + (bc0 ^ bswz));
                    bfr[0][p * 2 + 0][0] = r0; bfr[0][p * 2 + 0][1] = r1;
                    bfr[0][p * 2 + 1][0] = r2; bfr[0][p * 2 + 1][1] = r3;
                }

                #pragma unroll
                for (int ks = 0; ks < KC / 16; ks++) {
                    const int cur = ks & 1, nxt = cur ^ 1;
                    if (ks + 1 < KC / 16) {
                        const uint32_t kb2 = (uint32_t)(ks + 1) * 32;
                        #pragma unroll
                        for (int mf = 0; mf < 4; mf++)
                            LDMATRIX_X4(af[nxt][mf][0], af[nxt][mf][1], af[nxt][mf][2], af[nxt][mf][3],
                                        abase + mf * 2048 + ((ac0 + kb2) ^ aswz));
                        #pragma unroll
                        for (int p = 0; p < 4; p++) {
                            unsigned r0, r1, r2, r3;
                            LDMATRIX_X4(r0, r1, r2, r3, bbase + p * 2048 + ((bc0 + kb2) ^ bswz));
                            bfr[nxt][p * 2 + 0][0] = r0; bfr[nxt][p * 2 + 0][1] = r1;
                            bfr[nxt][p * 2 + 1][0] = r2; bfr[nxt][p * 2 + 1][1] = r3;
                        }
                    }
                    #pragma unroll
                    for (int mf = 0; mf < 4; mf++)
                        #pragma unroll
                        for (int nf = 0; nf < 8; nf++)
                            asm volatile(
                                "mma.sync.aligned.m16n8k16.row.col.f32.bf16.bf16.f32 "
                                "{%0,%1,%2,%3},{%4,%5,%6,%7},{%8,%9},{%0,%1,%2,%3};"
                                : "+f"(c[mf][nf][0]), "+f"(c[mf][nf][1]),
                                  "+f"(c[mf][nf][2]), "+f"(c[mf][nf][3])
                                : "r"(af[cur][mf][0]), "r"(af[cur][mf][1]),
                                  "r"(af[cur][mf][2]), "r"(af[cur][mf][3]),
                                  "r"(bfr[cur][nf][0]), "r"(bfr[cur][nf][1]));
                }
            }

            __syncwarp();
            if (lane == 0) MBARRIER_ARRIVE(mbE[stage]);
        }

        // -------- epilogue (active quadrants only) --------
        if (wAct) {
            const int rowSlotBase = i0 + wm * 64;
            const int colSlotBase = j0 + wn * 64;

            int rOK[4][2], rIdx[4][2];
            #pragma unroll
            for (int mf = 0; mf < 4; mf++)
                #pragma unroll
                for (int y = 0; y < 2; y++) {
                    int slot = rowSlotBase + mf * 16 + g + 8 * y;
                    rOK[mf][y] = (slot < c1);
                    rIdx[mf][y] = rOK[mf][y] ? g_idx1[b * S_ + slot] : 0;
                }
            int cOK[8][2], cIdx[8][2];
            #pragma unroll
            for (int nf = 0; nf < 8; nf++)
                #pragma unroll
                for (int x = 0; x < 2; x++) {
                    int slot = colSlotBase + nf * 8 + 2 * tg + x;
                    cOK[nf][x] = (slot < c2);
                    cIdx[nf][x] = cOK[nf][x] ? g_idx2[b * S_ + slot] : 0;
                }

            #pragma unroll
            for (int mf = 0; mf < 4; mf++)
                #pragma unroll
                for (int y = 0; y < 2; y++) {
                    float r = -INFINITY;
                    #pragma unroll
                    for (int nf = 0; nf < 8; nf++) {
                        if (cOK[nf][0]) r = fmaxf(r, c[mf][nf][y * 2 + 0]);
                        if (cOK[nf][1]) r = fmaxf(r, c[mf][nf][y * 2 + 1]);
                    }
                    r = fmaxf(r, __shfl_xor_sync(0xffffffffu, r, 1));
                    r = fmaxf(r, __shfl_xor_sync(0xffffffffu, r, 2));
                    if (tg == 0 && rOK[mf][y])
                        atomicMax(&g_rowmax[b * S_ + rIdx[mf][y]], fmap(r));
                }

            #pragma unroll
            for (int nf = 0; nf < 8; nf++)
                #pragma unroll
                for (int x = 0; x < 2; x++) {
                    float cm = -INFINITY;
                    #pragma unroll
                    for (int mf = 0; mf < 4; mf++) {
                        if (rOK[mf][0]) cm = fmaxf(cm, c[mf][nf][0 * 2 + x]);
                        if (rOK[mf][1]) cm = fmaxf(cm, c[mf][nf][1 * 2 + x]);
                    }
                    cm = fmaxf(cm, __shfl_xor_sync(0xffffffffu, cm, 4));
                    cm = fmaxf(cm, __shfl_xor_sync(0xffffffffu, cm, 8));
                    cm = fmaxf(cm, __shfl_xor_sync(0xffffffffu, cm, 16));
                    if (g == 0 && cOK[nf][x])
                        atomicMax(&g_colmax[b * S_ + cIdx[nf][x]], fmap(cm));
                }
        }
    }

    // -------- finalize: 16th-arriving CTA of this batch computes score --------
    __shared__ float fsum[4];
    __shared__ int   fcnt[4];
    __shared__ int   s_old;

    __threadfence();
    __syncthreads();
    if (tid == 0) s_old = atomicAdd(&g_arrive[b], 1);
    __syncthreads();
    if (s_old == 15) {
        __threadfence();
        float sum = 0.0f;
        int cnt = 0;
        for (int j = tid; j < S_; j += 128) {
            int a1 = mask1[b * S_ + j];
            int a2 = mask2[b * S_ + j];
            cnt += a1 + a2;
            if (a1) sum += fumap(__ldcg(&g_rowmax[b * S_ + j]));
            if (a2) sum += fumap(__ldcg(&g_colmax[b * S_ + j]));
        }
        #pragma unroll
        for (int o = 16; o; o >>= 1) {
            sum += __shfl_xor_sync(0xffffffffu, sum, o);
            cnt += __shfl_xor_sync(0xffffffffu, cnt, o);
        }
        if (lane == 0) { fsum[warp] = sum; fcnt[warp] = cnt; }
        __syncthreads();
        if (tid == 0) {
            float ts = 0.f; int tc = 0;
            #pragma unroll
            for (int i = 0; i < 4; i++) { ts += fsum[i]; tc += fcnt[i]; }
            out[b] = ts / fmaxf((float)tc, 1.0f);
            g_arrive[b] = 0;   // reset for graph replay
        }
    }
}

// ---------------- launch ----------------
extern "C" void kernel_launch(void* const* d_in, const int* in_sizes, int n_in,
                              void* d_out, int out_size) {
    const float* emb1 = (const float*)d_in[0];
    const float* emb2 = (const float*)d_in[1];
    const int*   mask1 = (const int*)d_in[2];
    const int*   mask2 = (const int*)d_in[3];
    float* out = (float*)d_out;

    cudaFuncSetAttribute(gemm_max_kernel,
                         cudaFuncAttributeMaxDynamicSharedMemorySize, SMEM_TOTAL);

    normalize_kernel<<<dim3(2048, 2), 256>>>(emb1, emb2, mask1, mask2);
    gemm_max_kernel<<<dim3(4, 4, B_), 128, SMEM_TOTAL>>>(mask1, mask2, out);
}

// round 15
// speedup vs baseline: 1.0579x; 1.0579x over previous
#include <cuda_runtime.h>
#include <cuda_bf16.h>
#include <cstdint>

#define B_   32
#define S_   512
#define D_   768
#define EPS_ 1e-8f

#define KC    64
#define NCH   (D_ / KC)          // 12

// ---------------- device scratch ----------------
// compacted, chunk-tiled, pre-swizzled bf16: [b][kc][slot][64], 128B rows
__device__ __align__(16) __nv_bfloat16 g_n1t[B_ * S_ * D_];
__device__ __align__(16) __nv_bfloat16 g_n2t[B_ * S_ * D_];
__device__ int g_idx1[B_ * S_], g_idx2[B_ * S_];    // slot -> original row
__device__ int g_cnt1[B_], g_cnt2[B_];
__device__ unsigned g_rowmax[B_ * S_];   // order-preserving mapped fp32
__device__ unsigned g_colmax[B_ * S_];
__device__ int      g_arrive[B_];

// ---------------- helpers ----------------
__device__ __forceinline__ uint32_t smem_u32(const void* p) {
    uint32_t a;
    asm("{ .reg .u64 t; cvta.to.shared.u64 t, %1; cvt.u32.u64 %0, t; }" : "=r"(a) : "l"(p));
    return a;
}
__device__ __forceinline__ unsigned fmap(float x) {
    int i = __float_as_int(x);
    return (unsigned)(i ^ ((i >> 31) | 0x80000000));
}
__device__ __forceinline__ float fumap(unsigned u) {
    int i = (int)(u ^ ((u & 0x80000000u) ? 0x80000000u : 0xFFFFFFFFu));
    return __int_as_float(i);
}

#define MBARRIER_INIT(addr, cnt) \
    asm volatile("mbarrier.init.shared.b64 [%0], %1;" :: "r"(addr), "r"(cnt) : "memory")
#define MBARRIER_EXPECT_TX(addr, bytes) \
    asm volatile("mbarrier.arrive.expect_tx.shared.b64 _, [%0], %1;" :: "r"(addr), "r"(bytes) : "memory")
#define MBARRIER_ARRIVE(addr) \
    asm volatile("mbarrier.arrive.shared.b64 _, [%0];" :: "r"(addr) : "memory")
#define MBARRIER_WAIT_PARITY(mbar_addr, phase_parity) do {                          \
    uint32_t _mbar = (uint32_t)(mbar_addr);                                         \
    uint32_t _par  = (uint32_t)(phase_parity);                                      \
    asm volatile(                                                                   \
        "{\n\t.reg .pred P1;\n\t"                                                   \
        "WAIT_LOOP_%=:\n\t"                                                         \
        "mbarrier.try_wait.parity.acquire.cta.shared::cta.b64 P1, [%0], %1, 0x989680;\n\t" \
        "@P1 bra.uni WAIT_DONE_%=;\n\t"                                             \
        "bra.uni WAIT_LOOP_%=;\n\t"                                                 \
        "WAIT_DONE_%=:\n\t}"                                                        \
        :: "r"(_mbar), "r"(_par) : "memory");                                       \
} while (0)

#define BULK_LOAD(dst, src, size, mbar) \
    asm volatile("cp.async.bulk.shared::cluster.global.mbarrier::complete_tx::bytes " \
                 "[%0], [%1], %2, [%3];" \
                 :: "r"(dst), "l"(src), "r"(size), "r"(mbar) : "memory")

#define LDMATRIX_X4(r0, r1, r2, r3, addr) \
    asm volatile("ldmatrix.sync.aligned.m8n8.x4.shared.b16 {%0,%1,%2,%3}, [%4];" \
                 : "=r"(r0), "=r"(r1), "=r"(r2), "=r"(r3) : "r"(addr))

// ---------------- kernel 1: normalize valid rows + in-block mask prefix ----------
// block 256 = 8 warps = 8 rows of one batch; each block re-derives its batch's
// 512-entry mask prefix (ballot scan) — no separate prefix kernel.
__global__ __launch_bounds__(256) void normalize_kernel(const float* __restrict__ e1,
                                                        const float* __restrict__ e2,
                                                        const int* __restrict__ mask1,
                                                        const int* __restrict__ mask2) {
    const int lane = threadIdx.x & 31;
    const int wrp  = threadIdx.x >> 5;
    const int grow = blockIdx.x * 8 + wrp;      // 0..16383
    const int b    = grow >> 9;
    const int r    = grow & 511;
    const int side = blockIdx.y;

    if (side == 0 && blockIdx.x < 64) {
        int t = blockIdx.x * 256 + threadIdx.x;   // covers exactly 16384
        g_rowmax[t] = 0u;
        g_colmax[t] = 0u;
        if (t < B_) g_arrive[t] = 0;
    }

    const int* m = side ? mask2 : mask1;

    __shared__ unsigned sball[16];
    __shared__ int segoff[16];

    {   // block-wide ballot scan of this batch's 512 mask entries
        int ra = threadIdx.x;                     // rows 0..255 and 256..511
        int va = (m[b * S_ + ra] != 0);
        int vb = (m[b * S_ + ra + 256] != 0);
        unsigned ba = __ballot_sync(0xffffffffu, va);
        unsigned bb = __ballot_sync(0xffffffffu, vb);
        if (lane == 0) { sball[wrp] = ba; sball[8 + wrp] = bb; }
    }
    __syncthreads();
    if (threadIdx.x == 0) {
        int run = 0;
        #pragma unroll
        for (int i = 0; i < 16; i++) { segoff[i] = run; run += __popc(sball[i]); }
        if (side == 0) g_cnt1[b] = run; else g_cnt2[b] = run;   // redundant same-value writes
    }
    __syncthreads();

    const int seg = r >> 5, bit = r & 31;
    if (!((sball[seg] >> bit) & 1u)) return;
    const int slot = segoff[seg] + __popc(sball[seg] & ((1u << bit) - 1u));
    if (lane == 0) (side ? g_idx2 : g_idx1)[b * S_ + slot] = r;

    const float* src = (side ? e2 : e1) + (size_t)grow * D_;
    __nv_bfloat16* dstBase = side ? g_n2t : g_n1t;

    float4 v[6];
    float ss = 0.0f;
    #pragma unroll
    for (int k = 0; k < 6; k++) {
        v[k] = __ldcs((const float4*)(src + lane * 4 + k * 128));
        ss += v[k].x * v[k].x + v[k].y * v[k].y + v[k].z * v[k].z + v[k].w * v[k].w;
    }
    #pragma unroll
    for (int o = 16; o; o >>= 1) ss += __shfl_xor_sync(0xffffffffu, ss, o);

    const float s = 1.0f / fmaxf(sqrtf(ss), EPS_);
    const int swz = (slot & 7) << 3;              // bf16-unit swizzle within 64-col row

    #pragma unroll
    for (int k = 0; k < 6; k++) {
        int cg = lane * 4 + k * 128;
        int kc = cg >> 6;
        int c  = cg & 63;
        size_t idx = ((size_t)(b * NCH + kc) * S_ + slot) * 64 + (size_t)(c ^ swz);
        *(__nv_bfloat162*)(dstBase + idx)     = __floats2bfloat162_rn(v[k].x * s, v[k].y * s);
        *(__nv_bfloat162*)(dstBase + idx + 2) = __floats2bfloat162_rn(v[k].z * s, v[k].w * s);
    }
}

// ---------------- kernel 2: compacted bulk-copy HMMA GEMM ----------------
// CTA tile 128x128, 4 warps 2(m)x2(n), warp tile 64x64, mma m16n8k16 bf16.
// grid (4,4,32); CTAs beyond the compacted counts exit to finalize-arrive.
// ALL warps of an active CTA compute unconditionally (compute paces the loads;
// R14's quadrant skip exposed the bulk copies and regressed).
#define TILE_BYTES  16384                 // 128 rows x 128B (A and B)
#define STAGE_BYTES (2 * TILE_BYTES)
#define SM_BUF      1024
#define SMEM_TOTAL  (SM_BUF + 3 * STAGE_BYTES)   // 99328

__global__ __launch_bounds__(128, 2) void gemm_max_kernel(const int* __restrict__ mask1,
                                                          const int* __restrict__ mask2,
                                                          float* __restrict__ out) {
    extern __shared__ char smem[];
    const uint32_t sbase = smem_u32(smem);

    const int tid  = threadIdx.x;
    const int lane = tid & 31;
    const int g    = lane >> 2;
    const int tg   = lane & 3;
    const int warp = tid >> 5;        // 0..3
    const int wm   = warp >> 1;       // 0..1
    const int wn   = warp & 1;        // 0..1

    const int b  = blockIdx.z;
    const int i0 = blockIdx.y * 128;
    const int j0 = blockIdx.x * 128;
    const int bid = blockIdx.x + 4 * blockIdx.y + 16 * b;
    const int off = bid % NCH;

    const int c1 = g_cnt1[b];
    const int c2 = g_cnt2[b];
    const bool active = (i0 < c1) && (j0 < c2);

    if (active) {
        float c[4][8][4];
        #pragma unroll
        for (int mf = 0; mf < 4; mf++)
            #pragma unroll
            for (int nf = 0; nf < 8; nf++)
                #pragma unroll
                for (int e = 0; e < 4; e++) c[mf][nf][e] = 0.0f;

        uint32_t mbF[3], mbE[3], sA[3], sB[3];
        #pragma unroll
        for (int s = 0; s < 3; s++) {
            mbF[s] = sbase + s * 8;
            mbE[s] = sbase + 24 + s * 8;
            sA[s] = sbase + SM_BUF + s * STAGE_BYTES;
            sB[s] = sA[s] + TILE_BYTES;
        }

        if (tid == 0) {
            #pragma unroll
            for (int s = 0; s < 3; s++) {
                MBARRIER_INIT(mbF[s], 1);
                MBARRIER_INIT(mbE[s], 4);         // one arrive per warp
            }
        }
        __syncthreads();

        const __nv_bfloat16* gA0 = g_n1t + ((size_t)(b * NCH) * S_ + i0) * 64;
        const __nv_bfloat16* gB0 = g_n2t + ((size_t)(b * NCH) * S_ + j0) * 64;
        const size_t CH_STRIDE = (size_t)S_ * 64;

        if (tid == 0) {
            #pragma unroll
            for (int p = 0; p < 2; p++) {
                const int cc = (p + off) % NCH;
                MBARRIER_EXPECT_TX(mbF[p], STAGE_BYTES);
                BULK_LOAD(sA[p], gA0 + (size_t)cc * CH_STRIDE, TILE_BYTES, mbF[p]);
                BULK_LOAD(sB[p], gB0 + (size_t)cc * CH_STRIDE, TILE_BYTES, mbF[p]);
            }
        }

        const int ar = wm * 64 + (lane & 15);
        const uint32_t arow = (uint32_t)ar * 128;
        const uint32_t aswz = (uint32_t)(ar & 7) << 4;
        const uint32_t ac0  = (uint32_t)(lane >> 4) * 16;

        const int br = wn * 64 + (lane & 7) + ((lane >> 4) << 3);
        const uint32_t brow = (uint32_t)br * 128;
        const uint32_t bswz = (uint32_t)(br & 7) << 4;
        const uint32_t bc0  = (uint32_t)((lane >> 3) & 1) * 16;

        unsigned af[2][4][4], bfr[2][8][2];

        #pragma unroll 1
        for (int ch = 0; ch < NCH; ch++) {
            const int stage = ch % 3;

            if (tid == 0 && ch + 2 < NCH) {
                const int cn = ch + 2;
                const int s2 = cn % 3;
                MBARRIER_WAIT_PARITY(mbE[s2], ((cn / 3) & 1) ^ 1);
                const int cc2 = (cn + off) % NCH;
                MBARRIER_EXPECT_TX(mbF[s2], STAGE_BYTES);
                BULK_LOAD(sA[s2], gA0 + (size_t)cc2 * CH_STRIDE, TILE_BYTES, mbF[s2]);
                BULK_LOAD(sB[s2], gB0 + (size_t)cc2 * CH_STRIDE, TILE_BYTES, mbF[s2]);
            }

            MBARRIER_WAIT_PARITY(mbF[stage], (ch / 3) & 1);

            const uint32_t abase = sA[stage] + arow;
            const uint32_t bbase = sB[stage] + brow;

            #pragma unroll
            for (int mf = 0; mf < 4; mf++)
                LDMATRIX_X4(af[0][mf][0], af[0][mf][1], af[0][mf][2], af[0][mf][3],
                            abase + mf * 2048 + (ac0 ^ aswz));
            #pragma unroll
            for (int p = 0; p < 4; p++) {
                unsigned r0, r1, r2, r3;
                LDMATRIX_X4(r0, r1, r2, r3, bbase + p * 2048 + (bc0 ^ bswz));
                bfr[0][p * 2 + 0][0] = r0; bfr[0][p * 2 + 0][1] = r1;
                bfr[0][p * 2 + 1][0] = r2; bfr[0][p * 2 + 1][1] = r3;
            }

            #pragma unroll
            for (int ks = 0; ks < KC / 16; ks++) {
                const int cur = ks & 1, nxt = cur ^ 1;
                if (ks + 1 < KC / 16) {
                    const uint32_t kb2 = (uint32_t)(ks + 1) * 32;
                    #pragma unroll
                    for (int mf = 0; mf < 4; mf++)
                        LDMATRIX_X4(af[nxt][mf][0], af[nxt][mf][1], af[nxt][mf][2], af[nxt][mf][3],
                                    abase + mf * 2048 + ((ac0 + kb2) ^ aswz));
                    #pragma unroll
                    for (int p = 0; p < 4; p++) {
                        unsigned r0, r1, r2, r3;
                        LDMATRIX_X4(r0, r1, r2, r3, bbase + p * 2048 + ((bc0 + kb2) ^ bswz));
                        bfr[nxt][p * 2 + 0][0] = r0; bfr[nxt][p * 2 + 0][1] = r1;
                        bfr[nxt][p * 2 + 1][0] = r2; bfr[nxt][p * 2 + 1][1] = r3;
                    }
                }
                #pragma unroll
                for (int mf = 0; mf < 4; mf++)
                    #pragma unroll
                    for (int nf = 0; nf < 8; nf++)
                        asm volatile(
                            "mma.sync.aligned.m16n8k16.row.col.f32.bf16.bf16.f32 "
                            "{%0,%1,%2,%3},{%4,%5,%6,%7},{%8,%9},{%0,%1,%2,%3};"
                            : "+f"(c[mf][nf][0]), "+f"(c[mf][nf][1]),
                              "+f"(c[mf][nf][2]), "+f"(c[mf][nf][3])
                            : "r"(af[cur][mf][0]), "r"(af[cur][mf][1]),
                              "r"(af[cur][mf][2]), "r"(af[cur][mf][3]),
                              "r"(bfr[cur][nf][0]), "r"(bfr[cur][nf][1]));
            }

            __syncwarp();
            if (lane == 0) MBARRIER_ARRIVE(mbE[stage]);
        }

        // -------- epilogue: validity = slot < count; atomics via index map --------
        const int rowSlotBase = i0 + wm * 64;
        const int colSlotBase = j0 + wn * 64;

        int rOK[4][2], rIdx[4][2];
        #pragma unroll
        for (int mf = 0; mf < 4; mf++)
            #pragma unroll
            for (int y = 0; y < 2; y++) {
                int slot = rowSlotBase + mf * 16 + g + 8 * y;
                rOK[mf][y] = (slot < c1);
                rIdx[mf][y] = rOK[mf][y] ? g_idx1[b * S_ + slot] : 0;
            }
        int cOK[8][2], cIdx[8][2];
        #pragma unroll
        for (int nf = 0; nf < 8; nf++)
            #pragma unroll
            for (int x = 0; x < 2; x++) {
                int slot = colSlotBase + nf * 8 + 2 * tg + x;
                cOK[nf][x] = (slot < c2);
                cIdx[nf][x] = cOK[nf][x] ? g_idx2[b * S_ + slot] : 0;
            }

        #pragma unroll
        for (int mf = 0; mf < 4; mf++)
            #pragma unroll
            for (int y = 0; y < 2; y++) {
                float r = -INFINITY;
                #pragma unroll
                for (int nf = 0; nf < 8; nf++) {
                    if (cOK[nf][0]) r = fmaxf(r, c[mf][nf][y * 2 + 0]);
                    if (cOK[nf][1]) r = fmaxf(r, c[mf][nf][y * 2 + 1]);
                }
                r = fmaxf(r, __shfl_xor_sync(0xffffffffu, r, 1));
                r = fmaxf(r, __shfl_xor_sync(0xffffffffu, r, 2));
                if (tg == 0 && rOK[mf][y])
                    atomicMax(&g_rowmax[b * S_ + rIdx[mf][y]], fmap(r));
            }

        #pragma unroll
        for (int nf = 0; nf < 8; nf++)
            #pragma unroll
            for (int x = 0; x < 2; x++) {
                float cm = -INFINITY;
                #pragma unroll
                for (int mf = 0; mf < 4; mf++) {
                    if (rOK[mf][0]) cm = fmaxf(cm, c[mf][nf][0 * 2 + x]);
                    if (rOK[mf][1]) cm = fmaxf(cm, c[mf][nf][1 * 2 + x]);
                }
                cm = fmaxf(cm, __shfl_xor_sync(0xffffffffu, cm, 4));
                cm = fmaxf(cm, __shfl_xor_sync(0xffffffffu, cm, 8));
                cm = fmaxf(cm, __shfl_xor_sync(0xffffffffu, cm, 16));
                if (g == 0 && cOK[nf][x])
                    atomicMax(&g_colmax[b * S_ + cIdx[nf][x]], fmap(cm));
            }
    }

    // -------- finalize: 16th-arriving CTA of this batch computes score --------
    __shared__ float fsum[4];
    __shared__ int   fcnt[4];
    __shared__ int   s_old;

    __threadfence();
    __syncthreads();
    if (tid == 0) s_old = atomicAdd(&g_arrive[b], 1);
    __syncthreads();
    if (s_old == 15) {
        __threadfence();
        float sum = 0.0f;
        int cnt = 0;
        for (int j = tid; j < S_; j += 128) {
            int a1 = mask1[b * S_ + j];
            int a2 = mask2[b * S_ + j];
            cnt += a1 + a2;
            if (a1) sum += fumap(__ldcg(&g_rowmax[b * S_ + j]));
            if (a2) sum += fumap(__ldcg(&g_colmax[b * S_ + j]));
        }
        #pragma unroll
        for (int o = 16; o; o >>= 1) {
            sum += __shfl_xor_sync(0xffffffffu, sum, o);
            cnt += __shfl_xor_sync(0xffffffffu, cnt, o);
        }
        if (lane == 0) { fsum[warp] = sum; fcnt[warp] = cnt; }
        __syncthreads();
        if (tid == 0) {
            float ts = 0.f; int tc = 0;
            #pragma unroll
            for (int i = 0; i < 4; i++) { ts += fsum[i]; tc += fcnt[i]; }
            out[b] = ts / fmaxf((float)tc, 1.0f);
            g_arrive[b] = 0;   // reset for graph replay
        }
    }
}

// ---------------- launch ----------------
extern "C" void kernel_launch(void* const* d_in, const int* in_sizes, int n_in,
                              void* d_out, int out_size) {
    const float* emb1 = (const float*)d_in[0];
    const float* emb2 = (const float*)d_in[1];
    const int*   mask1 = (const int*)d_in[2];
    const int*   mask2 = (const int*)d_in[3];
    float* out = (float*)d_out;

    cudaFuncSetAttribute(gemm_max_kernel,
                         cudaFuncAttributeMaxDynamicSharedMemorySize, SMEM_TOTAL);

    normalize_kernel<<<dim3(2048, 2), 256>>>(emb1, emb2, mask1, mask2);
    gemm_max_kernel<<<dim3(4, 4, B_), 128, SMEM_TOTAL>>>(mask1, mask2, out);
}

// round 16
// speedup vs baseline: 1.0988x; 1.0386x over previous
#include <cuda_runtime.h>
#include <cuda_bf16.h>
#include <cstdint>

#define B_   32
#define S_   512
#define D_   768
#define EPS_ 1e-8f

#define KC    64
#define NCH   (D_ / KC)          // 12

// ---------------- device scratch ----------------
// compacted, chunk-tiled, pre-swizzled bf16: [b][kc][slot][64], 128B rows
__device__ __align__(16) __nv_bfloat16 g_n1t[B_ * S_ * D_];
__device__ __align__(16) __nv_bfloat16 g_n2t[B_ * S_ * D_];
__device__ int g_idx1[B_ * S_], g_idx2[B_ * S_];    // slot -> original row
__device__ int g_cnt1[B_], g_cnt2[B_];
__device__ unsigned g_rowmax[B_ * S_];   // order-preserving mapped fp32
__device__ unsigned g_colmax[B_ * S_];
__device__ int      g_arrive[B_];

// ---------------- helpers ----------------
__device__ __forceinline__ uint32_t smem_u32(const void* p) {
    uint32_t a;
    asm("{ .reg .u64 t; cvta.to.shared.u64 t, %1; cvt.u32.u64 %0, t; }" : "=r"(a) : "l"(p));
    return a;
}
__device__ __forceinline__ unsigned fmap(float x) {
    int i = __float_as_int(x);
    return (unsigned)(i ^ ((i >> 31) | 0x80000000));
}
__device__ __forceinline__ float fumap(unsigned u) {
    int i = (int)(u ^ ((u & 0x80000000u) ? 0x80000000u : 0xFFFFFFFFu));
    return __int_as_float(i);
}

#define MBARRIER_INIT(addr, cnt) \
    asm volatile("mbarrier.init.shared.b64 [%0], %1;" :: "r"(addr), "r"(cnt) : "memory")
#define MBARRIER_EXPECT_TX(addr, bytes) \
    asm volatile("mbarrier.arrive.expect_tx.shared.b64 _, [%0], %1;" :: "r"(addr), "r"(bytes) : "memory")
#define MBARRIER_ARRIVE(addr) \
    asm volatile("mbarrier.arrive.shared.b64 _, [%0];" :: "r"(addr) : "memory")
#define MBARRIER_WAIT_PARITY(mbar_addr, phase_parity) do {                          \
    uint32_t _mbar = (uint32_t)(mbar_addr);                                         \
    uint32_t _par  = (uint32_t)(phase_parity);                                      \
    asm volatile(                                                                   \
        "{\n\t.reg .pred P1;\n\t"                                                   \
        "WAIT_LOOP_%=:\n\t"                                                         \
        "mbarrier.try_wait.parity.acquire.cta.shared::cta.b64 P1, [%0], %1, 0x989680;\n\t" \
        "@P1 bra.uni WAIT_DONE_%=;\n\t"                                             \
        "bra.uni WAIT_LOOP_%=;\n\t"                                                 \
        "WAIT_DONE_%=:\n\t}"                                                        \
        :: "r"(_mbar), "r"(_par) : "memory");                                       \
} while (0)

#define BULK_LOAD(dst, src, size, mbar) \
    asm volatile("cp.async.bulk.shared::cluster.global.mbarrier::complete_tx::bytes " \
                 "[%0], [%1], %2, [%3];" \
                 :: "r"(dst), "l"(src), "r"(size), "r"(mbar) : "memory")

#define LDMATRIX_X4(r0, r1, r2, r3, addr) \
    asm volatile("ldmatrix.sync.aligned.m8n8.x4.shared.b16 {%0,%1,%2,%3}, [%4];" \
                 : "=r"(r0), "=r"(r1), "=r"(r2), "=r"(r3) : "r"(addr))

// ---------------- kernel 1: normalize valid rows + in-block mask prefix ----------
__global__ __launch_bounds__(256) void normalize_kernel(const float* __restrict__ e1,
                                                        const float* __restrict__ e2,
                                                        const int* __restrict__ mask1,
                                                        const int* __restrict__ mask2) {
    const int lane = threadIdx.x & 31;
    const int wrp  = threadIdx.x >> 5;
    const int grow = blockIdx.x * 8 + wrp;      // 0..16383
    const int b    = grow >> 9;
    const int r    = grow & 511;
    const int side = blockIdx.y;

    if (side == 0 && blockIdx.x < 64) {
        int t = blockIdx.x * 256 + threadIdx.x;   // covers exactly 16384
        g_rowmax[t] = 0u;
        g_colmax[t] = 0u;
        if (t < B_) g_arrive[t] = 0;
    }

    const int* m = side ? mask2 : mask1;

    __shared__ unsigned sball[16];
    __shared__ int segoff[16];

    {   // block-wide ballot scan of this batch's 512 mask entries
        int ra = threadIdx.x;
        int va = (m[b * S_ + ra] != 0);
        int vb = (m[b * S_ + ra + 256] != 0);
        unsigned ba = __ballot_sync(0xffffffffu, va);
        unsigned bb = __ballot_sync(0xffffffffu, vb);
        if (lane == 0) { sball[wrp] = ba; sball[8 + wrp] = bb; }
    }
    __syncthreads();
    if (threadIdx.x == 0) {
        int run = 0;
        #pragma unroll
        for (int i = 0; i < 16; i++) { segoff[i] = run; run += __popc(sball[i]); }
        if (side == 0) g_cnt1[b] = run; else g_cnt2[b] = run;
    }
    __syncthreads();

    const int seg = r >> 5, bit = r & 31;
    if (!((sball[seg] >> bit) & 1u)) return;
    const int slot = segoff[seg] + __popc(sball[seg] & ((1u << bit) - 1u));
    if (lane == 0) (side ? g_idx2 : g_idx1)[b * S_ + slot] = r;

    const float* src = (side ? e2 : e1) + (size_t)grow * D_;
    __nv_bfloat16* dstBase = side ? g_n2t : g_n1t;

    float4 v[6];
    float ss = 0.0f;
    #pragma unroll
    for (int k = 0; k < 6; k++) {
        v[k] = __ldcs((const float4*)(src + lane * 4 + k * 128));
        ss += v[k].x * v[k].x + v[k].y * v[k].y + v[k].z * v[k].z + v[k].w * v[k].w;
    }
    #pragma unroll
    for (int o = 16; o; o >>= 1) ss += __shfl_xor_sync(0xffffffffu, ss, o);

    const float s = 1.0f / fmaxf(sqrtf(ss), EPS_);
    const int swz = (slot & 7) << 3;

    #pragma unroll
    for (int k = 0; k < 6; k++) {
        int cg = lane * 4 + k * 128;
        int kc = cg >> 6;
        int c  = cg & 63;
        size_t idx = ((size_t)(b * NCH + kc) * S_ + slot) * 64 + (size_t)(c ^ swz);
        *(__nv_bfloat162*)(dstBase + idx)     = __floats2bfloat162_rn(v[k].x * s, v[k].y * s);
        *(__nv_bfloat162*)(dstBase + idx + 2) = __floats2bfloat162_rn(v[k].z * s, v[k].w * s);
    }
}

// ---------------- kernel 2: compacted bulk-copy HMMA GEMM, 64x128 tiles ----------
// CTA tile 64(M)x128(N), 4 warps 2(m)x2(n), warp tile 32x64, mma m16n8k16 bf16.
// Stage 24KB, 3 stages -> 3 CTAs/SM resident. grid (4 N, 8 M, 32 B).
#define TILE_A_BYTES  8192                // 64 rows x 128B
#define TILE_B_BYTES  16384               // 128 rows x 128B
#define STAGE_BYTES   (TILE_A_BYTES + TILE_B_BYTES)   // 24576
#define SM_BUF        1024
#define SMEM_TOTAL    (SM_BUF + 3 * STAGE_BYTES)      // 74752

__global__ __launch_bounds__(128, 3) void gemm_max_kernel(const int* __restrict__ mask1,
                                                          const int* __restrict__ mask2,
                                                          float* __restrict__ out) {
    extern __shared__ char smem[];
    const uint32_t sbase = smem_u32(smem);

    const int tid  = threadIdx.x;
    const int lane = tid & 31;
    const int g    = lane >> 2;
    const int tg   = lane & 3;
    const int warp = tid >> 5;        // 0..3
    const int wm   = warp >> 1;       // 0..1 (32-row halves)
    const int wn   = warp & 1;        // 0..1 (64-col halves)

    const int b  = blockIdx.z;
    const int i0 = blockIdx.y * 64;
    const int j0 = blockIdx.x * 128;
    const int bid = blockIdx.x + 4 * blockIdx.y + 32 * b;
    const int off = bid % NCH;

    const int c1 = g_cnt1[b];
    const int c2 = g_cnt2[b];
    const bool active = (i0 < c1) && (j0 < c2);

    if (active) {
        float c[2][8][4];
        #pragma unroll
        for (int mf = 0; mf < 2; mf++)
            #pragma unroll
            for (int nf = 0; nf < 8; nf++)
                #pragma unroll
                for (int e = 0; e < 4; e++) c[mf][nf][e] = 0.0f;

        uint32_t mbF[3], mbE[3], sA[3], sB[3];
        #pragma unroll
        for (int s = 0; s < 3; s++) {
            mbF[s] = sbase + s * 8;
            mbE[s] = sbase + 24 + s * 8;
            sA[s] = sbase + SM_BUF + s * STAGE_BYTES;
            sB[s] = sA[s] + TILE_A_BYTES;
        }

        if (tid == 0) {
            #pragma unroll
            for (int s = 0; s < 3; s++) {
                MBARRIER_INIT(mbF[s], 1);
                MBARRIER_INIT(mbE[s], 4);         // one arrive per warp
            }
        }
        __syncthreads();

        const __nv_bfloat16* gA0 = g_n1t + ((size_t)(b * NCH) * S_ + i0) * 64;
        const __nv_bfloat16* gB0 = g_n2t + ((size_t)(b * NCH) * S_ + j0) * 64;
        const size_t CH_STRIDE = (size_t)S_ * 64;

        if (tid == 0) {
            #pragma unroll
            for (int p = 0; p < 2; p++) {
                const int cc = (p + off) % NCH;
                MBARRIER_EXPECT_TX(mbF[p], STAGE_BYTES);
                BULK_LOAD(sA[p], gA0 + (size_t)cc * CH_STRIDE, TILE_A_BYTES, mbF[p]);
                BULK_LOAD(sB[p], gB0 + (size_t)cc * CH_STRIDE, TILE_B_BYTES, mbF[p]);
            }
        }

        const int ar = wm * 32 + (lane & 15);
        const uint32_t arow = (uint32_t)ar * 128;
        const uint32_t aswz = (uint32_t)(ar & 7) << 4;
        const uint32_t ac0  = (uint32_t)(lane >> 4) * 16;

        const int br = wn * 64 + (lane & 7) + ((lane >> 4) << 3);
        const uint32_t brow = (uint32_t)br * 128;
        const uint32_t bswz = (uint32_t)(br & 7) << 4;
        const uint32_t bc0  = (uint32_t)((lane >> 3) & 1) * 16;

        unsigned af[2][2][4], bfr[2][8][2];

        #pragma unroll 1
        for (int ch = 0; ch < NCH; ch++) {
            const int stage = ch % 3;

            if (tid == 0 && ch + 2 < NCH) {
                const int cn = ch + 2;
                const int s2 = cn % 3;
                MBARRIER_WAIT_PARITY(mbE[s2], ((cn / 3) & 1) ^ 1);
                const int cc2 = (cn + off) % NCH;
                MBARRIER_EXPECT_TX(mbF[s2], STAGE_BYTES);
                BULK_LOAD(sA[s2], gA0 + (size_t)cc2 * CH_STRIDE, TILE_A_BYTES, mbF[s2]);
                BULK_LOAD(sB[s2], gB0 + (size_t)cc2 * CH_STRIDE, TILE_B_BYTES, mbF[s2]);
            }

            MBARRIER_WAIT_PARITY(mbF[stage], (ch / 3) & 1);

            const uint32_t abase = sA[stage] + arow;
            const uint32_t bbase = sB[stage] + brow;

            #pragma unroll
            for (int mf = 0; mf < 2; mf++)
                LDMATRIX_X4(af[0][mf][0], af[0][mf][1], af[0][mf][2], af[0][mf][3],
                            abase + mf * 2048 + (ac0 ^ aswz));
            #pragma unroll
            for (int p = 0; p < 4; p++) {
                unsigned r0, r1, r2, r3;
                LDMATRIX_X4(r0, r1, r2, r3, bbase + p * 2048 + (bc0 ^ bswz));
                bfr[0][p * 2 + 0][0] = r0; bfr[0][p * 2 + 0][1] = r1;
                bfr[0][p * 2 + 1][0] = r2; bfr[0][p * 2 + 1][1] = r3;
            }

            #pragma unroll
            for (int ks = 0; ks < KC / 16; ks++) {
                const int cur = ks & 1, nxt = cur ^ 1;
                if (ks + 1 < KC / 16) {
                    const uint32_t kb2 = (uint32_t)(ks + 1) * 32;
                    #pragma unroll
                    for (int mf = 0; mf < 2; mf++)
                        LDMATRIX_X4(af[nxt][mf][0], af[nxt][mf][1], af[nxt][mf][2], af[nxt][mf][3],
                                    abase + mf * 2048 + ((ac0 + kb2) ^ aswz));
                    #pragma unroll
                    for (int p = 0; p < 4; p++) {
                        unsigned r0, r1, r2, r3;
                        LDMATRIX_X4(r0, r1, r2, r3, bbase + p * 2048 + ((bc0 + kb2) ^ bswz));
                        bfr[nxt][p * 2 + 0][0] = r0; bfr[nxt][p * 2 + 0][1] = r1;
                        bfr[nxt][p * 2 + 1][0] = r2; bfr[nxt][p * 2 + 1][1] = r3;
                    }
                }
                #pragma unroll
                for (int mf = 0; mf < 2; mf++)
                    #pragma unroll
                    for (int nf = 0; nf < 8; nf++)
                        asm volatile(
                            "mma.sync.aligned.m16n8k16.row.col.f32.bf16.bf16.f32 "
                            "{%0,%1,%2,%3},{%4,%5,%6,%7},{%8,%9},{%0,%1,%2,%3};"
                            : "+f"(c[mf][nf][0]), "+f"(c[mf][nf][1]),
                              "+f"(c[mf][nf][2]), "+f"(c[mf][nf][3])
                            : "r"(af[cur][mf][0]), "r"(af[cur][mf][1]),
                              "r"(af[cur][mf][2]), "r"(af[cur][mf][3]),
                              "r"(bfr[cur][nf][0]), "r"(bfr[cur][nf][1]));
            }

            __syncwarp();
            if (lane == 0) MBARRIER_ARRIVE(mbE[stage]);
        }

        // -------- epilogue: validity = slot < count; atomics via index map --------
        const int rowSlotBase = i0 + wm * 32;
        const int colSlotBase = j0 + wn * 64;

        int rOK[2][2], rIdx[2][2];
        #pragma unroll
        for (int mf = 0; mf < 2; mf++)
            #pragma unroll
            for (int y = 0; y < 2; y++) {
                int slot = rowSlotBase + mf * 16 + g + 8 * y;
                rOK[mf][y] = (slot < c1);
                rIdx[mf][y] = rOK[mf][y] ? g_idx1[b * S_ + slot] : 0;
            }
        int cOK[8][2], cIdx[8][2];
        #pragma unroll
        for (int nf = 0; nf < 8; nf++)
            #pragma unroll
            for (int x = 0; x < 2; x++) {
                int slot = colSlotBase + nf * 8 + 2 * tg + x;
                cOK[nf][x] = (slot < c2);
                cIdx[nf][x] = cOK[nf][x] ? g_idx2[b * S_ + slot] : 0;
            }

        #pragma unroll
        for (int mf = 0; mf < 2; mf++)
            #pragma unroll
            for (int y = 0; y < 2; y++) {
                float r = -INFINITY;
                #pragma unroll
                for (int nf = 0; nf < 8; nf++) {
                    if (cOK[nf][0]) r = fmaxf(r, c[mf][nf][y * 2 + 0]);
                    if (cOK[nf][1]) r = fmaxf(r, c[mf][nf][y * 2 + 1]);
                }
                r = fmaxf(r, __shfl_xor_sync(0xffffffffu, r, 1));
                r = fmaxf(r, __shfl_xor_sync(0xffffffffu, r, 2));
                if (tg == 0 && rOK[mf][y])
                    atomicMax(&g_rowmax[b * S_ + rIdx[mf][y]], fmap(r));
            }

        #pragma unroll
        for (int nf = 0; nf < 8; nf++)
            #pragma unroll
            for (int x = 0; x < 2; x++) {
                float cm = -INFINITY;
                #pragma unroll
                for (int mf = 0; mf < 2; mf++) {
                    if (rOK[mf][0]) cm = fmaxf(cm, c[mf][nf][0 * 2 + x]);
                    if (rOK[mf][1]) cm = fmaxf(cm, c[mf][nf][1 * 2 + x]);
                }
                cm = fmaxf(cm, __shfl_xor_sync(0xffffffffu, cm, 4));
                cm = fmaxf(cm, __shfl_xor_sync(0xffffffffu, cm, 8));
                cm = fmaxf(cm, __shfl_xor_sync(0xffffffffu, cm, 16));
                if (g == 0 && cOK[nf][x])
                    atomicMax(&g_colmax[b * S_ + cIdx[nf][x]], fmap(cm));
            }
    }

    // -------- finalize: 32nd-arriving CTA of this batch computes score --------
    __shared__ float fsum[4];
    __shared__ int   fcnt[4];
    __shared__ int   s_old;

    __threadfence();
    __syncthreads();
    if (tid == 0) s_old = atomicAdd(&g_arrive[b], 1);
    __syncthreads();
    if (s_old == 31) {
        __threadfence();
        float sum = 0.0f;
        int cnt = 0;
        for (int j = tid; j < S_; j += 128) {
            int a1 = mask1[b * S_ + j];
            int a2 = mask2[b * S_ + j];
            cnt += a1 + a2;
            if (a1) sum += fumap(__ldcg(&g_rowmax[b * S_ + j]));
            if (a2) sum += fumap(__ldcg(&g_colmax[b * S_ + j]));
        }
        #pragma unroll
        for (int o = 16; o; o >>= 1) {
            sum += __shfl_xor_sync(0xffffffffu, sum, o);
            cnt += __shfl_xor_sync(0xffffffffu, cnt, o);
        }
        if (lane == 0) { fsum[warp] = sum; fcnt[warp] = cnt; }
        __syncthreads();
        if (tid == 0) {
            float ts = 0.f; int tc = 0;
            #pragma unroll
            for (int i = 0; i < 4; i++) { ts += fsum[i]; tc += fcnt[i]; }
            out[b] = ts / fmaxf((float)tc, 1.0f);
            g_arrive[b] = 0;   // reset for graph replay
        }
    }
}

// ---------------- launch ----------------
extern "C" void kernel_launch(void* const* d_in, const int* in_sizes, int n_in,
                              void* d_out, int out_size) {
    const float* emb1 = (const float*)d_in[0];
    const float* emb2 = (const float*)d_in[1];
    const int*   mask1 = (const int*)d_in[2];
    const int*   mask2 = (const int*)d_in[3];
    float* out = (float*)d_out;

    cudaFuncSetAttribute(gemm_max_kernel,
                         cudaFuncAttributeMaxDynamicSharedMemorySize, SMEM_TOTAL);

    normalize_kernel<<<dim3(2048, 2), 256>>>(emb1, emb2, mask1, mask2);
    gemm_max_kernel<<<dim3(4, 8, B_), 128, SMEM_TOTAL>>>(mask1, mask2, out);
}